// round 13
// baseline (speedup 1.0000x reference)
#include <cuda_runtime.h>
#include <cuda_fp16.h>
#include <math.h>

#define N_NODES 100000
#define DIN     512
#define NE      1600000
#define ET      (NE + N_NODES)   // edges + self loops
#define NEG_SLOPE 0.2f
#define NPART   ((N_NODES + 1023) / 1024)
#define WT_K    520              // padded per-n stride (halves)

// ---------------- scratch (device globals) -------------------------------------
__device__ __align__(128) __half g_Wt[64 * WT_K];              // W^T fragment-packed
__device__ __align__(128) __half g_Hh[(size_t)N_NODES * 64];   // fp16 messages L1
__device__ __align__(128) float  g_ald[N_NODES * 8];
__device__ __align__(128) __half g_h3h[(size_t)N_NODES * 16];  // fp16 messages L2
__device__ __align__(128) float  g_al2s[N_NODES];
__device__ __align__(128) float  g_al2d[N_NODES];
__device__ int g_esrc[ET];
__device__ int g_deg[N_NODES + NPART];
__device__ int g_off[N_NODES + 1];
__device__ int g_cur[N_NODES];

__device__ __forceinline__ float2 h2f2(unsigned u) {
    __half2 h = *reinterpret_cast<const __half2*>(&u);
    return __half22float2(h);
}

__device__ __forceinline__ int detect_is64(const int* ei32) {
    int allzero = 1;
#pragma unroll 8
    for (int i = 0; i < 64; i++)
        if (__ldg(&ei32[2 * i + 1]) != 0) { allzero = 0; break; }
    return allzero;
}

__device__ __forceinline__ void decode_edge(const void* ei, int is64, int e,
                                            int* s, int* d) {
    if (e < NE) {
        int sv, dv;
        if (is64) {
            const long long* p = (const long long*)ei;
            sv = (int)p[e];
            dv = (int)p[(size_t)NE + e];
        } else {
            const int* p = (const int*)ei;
            sv = p[e];
            dv = p[NE + e];
        }
        *s = min(max(sv, 0), N_NODES - 1);
        *d = min(max(dv, 0), N_NODES - 1);
    } else {
        *s = e - NE;
        *d = e - NE;
    }
}

__global__ void k_count(const void* __restrict__ ei) {
    int is64 = detect_is64((const int*)ei);
    int e = blockIdx.x * blockDim.x + threadIdx.x;
    if (e >= ET) return;
    int s, d;
    decode_edge(ei, is64, e, &s, &d);
    atomicAdd(&g_deg[d], 1);
}

__global__ __launch_bounds__(1024) void k_scan() {
    __shared__ int wsum[32];
    __shared__ int sbase;
    int t = threadIdx.x, b = blockIdx.x;
    if (t == 0) sbase = 0;
    int i = b * 1024 + t;
    int v = (i < N_NODES) ? g_deg[i] : 0;
    int x = v;
    int lane = t & 31, w = t >> 5;
#pragma unroll
    for (int o = 1; o < 32; o <<= 1) {
        int y = __shfl_up_sync(0xffffffffu, x, o);
        if (lane >= o) x += y;
    }
    if (lane == 31) wsum[w] = x;
    __syncthreads();
    if (t < 32) {
        int y = wsum[t];
#pragma unroll
        for (int o = 1; o < 32; o <<= 1) {
            int z = __shfl_up_sync(0xffffffffu, y, o);
            if (t >= o) y += z;
        }
        wsum[t] = y;
    }
    __syncthreads();

    volatile int* bs = (volatile int*)&g_deg[N_NODES];
    if (t == 0) bs[b] = wsum[31] + 1;
    if (t < b) {
        int pv;
        while ((pv = bs[t]) == 0) {}
        atomicAdd(&sbase, pv - 1);
    }
    __syncthreads();

    int excl = x - v + (w > 0 ? wsum[w - 1] : 0) + sbase;
    if (i < N_NODES) { g_off[i] = excl; g_cur[i] = excl; }
    if (b == 0 && t == 0) g_off[N_NODES] = ET;
}

__global__ void k_scatter(const void* __restrict__ ei) {
    int is64 = detect_is64((const int*)ei);
    int e = blockIdx.x * blockDim.x + threadIdx.x;
    if (e >= ET) return;
    int s, d;
    decode_edge(ei, is64, e, &s, &d);
    int pos = atomicAdd(&g_cur[d], 1);
    g_esrc[pos] = s;
}

// W^T fragment-packed: per n, per 16-k tile, thread q's B fragment (k=2q,2q+1,
// 2q+8,2q+9) is 4 contiguous halves -> one LDS.64 in the MMA loop.
__global__ void k_prep_w(const float* __restrict__ Wh) {
    int i = blockIdx.x * blockDim.x + threadIdx.x;
    if (i >= 64 * DIN) return;
    int n = i >> 9, k = i & 511;
    int l = n >> 3, f = n & 7;
    int kk = k & 15;
    int pos = (kk < 8) ? ((kk >> 1) * 4 + (kk & 1))
                       : (((kk - 8) >> 1) * 4 + 2 + (kk & 1));
    g_Wt[n * WT_K + (k >> 4) * 16 + pos] =
        __float2half(Wh[(size_t)l * (DIN * 8) + k * 8 + f]);
}

// ---------------- tensor-core GEMM (pipelined, double-buffered, packed-W) -------
#define GROWS 128
#define AKC   64
#define APAD  72
#define AS_TILE (GROWS * APAD)         // halves per As buffer
__global__ __launch_bounds__(256) void k_gemm(const float* __restrict__ x,
                                              const float* __restrict__ adst) {
    extern __shared__ char smem[];
    __half* As = (__half*)smem;                            // 2 x [128][72]
    __half* Ws = (__half*)(smem + 2 * AS_TILE * 2);        // [64][520] packed

    const int t = threadIdx.x;
    const int w = t >> 5;
    const int l = t & 31;
    const int row0 = blockIdx.x * GROWS;
    const int g = l >> 2;
    const int q = l & 3;

    {
        const uint4* src = (const uint4*)g_Wt;
#pragma unroll
        for (int i = 0; i < 16; i++) {
            int idx = i * 256 + t;
            int r = idx >> 6, c = idx & 63;
            *(uint4*)&Ws[r * WT_K + c * 8] = src[(r * WT_K + c * 8) >> 3];
        }
    }

    float acc[8][4];
#pragma unroll
    for (int n = 0; n < 8; n++)
#pragma unroll
        for (int j = 0; j < 4; j++) acc[n][j] = 0.f;

    const int arow = (l & 7) + ((l & 8) ? 8 : 0);
    const int acol = (l & 16) ? 8 : 0;

    const int pr_c4 = t & 15;
    const int pr_r0 = t >> 4;
    float4 pref[8];

    // prefetch + commit tile 0 into As[0]
#pragma unroll
    for (int i = 0; i < 8; i++) {
        int r = i * 16 + pr_r0;
        int rg = row0 + r; if (rg >= N_NODES) rg = N_NODES - 1;
        pref[i] = __ldcs((const float4*)&x[(size_t)rg * DIN + pr_c4 * 4]);
    }
#pragma unroll
    for (int i = 0; i < 8; i++) {
        int r = i * 16 + pr_r0;
        uint2 pk;
        *reinterpret_cast<__half2*>(&pk.x) = __floats2half2_rn(pref[i].x, pref[i].y);
        *reinterpret_cast<__half2*>(&pk.y) = __floats2half2_rn(pref[i].z, pref[i].w);
        *(uint2*)&As[r * APAD + pr_c4 * 4] = pk;
    }
    __syncthreads();   // Ws + As[0] ready

#pragma unroll
    for (int it = 0; it < DIN / AKC; it++) {
        const __half* Ac = As + (it & 1) * AS_TILE;
        // prefetch next tile (overlaps MMA below)
        if (it + 1 < DIN / AKC) {
#pragma unroll
            for (int i = 0; i < 8; i++) {
                int r = i * 16 + pr_r0;
                int rg = row0 + r; if (rg >= N_NODES) rg = N_NODES - 1;
                pref[i] = __ldcs((const float4*)&x[(size_t)rg * DIN + (it + 1) * AKC + pr_c4 * 4]);
            }
        }
        int kt = it * AKC;
#pragma unroll
        for (int k0 = 0; k0 < AKC; k0 += 16) {
            unsigned a0, a1, a2, a3;
            unsigned aaddr = __cvta_generic_to_shared(
                &Ac[(w * 16 + arow) * APAD + k0 + acol]);
            asm volatile("ldmatrix.sync.aligned.m8n8.x4.shared.b16 {%0,%1,%2,%3}, [%4];"
                         : "=r"(a0), "=r"(a1), "=r"(a2), "=r"(a3) : "r"(aaddr));
            int ktile = (kt + k0) >> 4;
#pragma unroll
            for (int nt = 0; nt < 8; nt++) {
                int n = nt * 8 + g;
                uint2 bb = *(const uint2*)&Ws[n * WT_K + ktile * 16 + q * 4];
                asm volatile(
                    "mma.sync.aligned.m16n8k16.row.col.f32.f16.f16.f32 "
                    "{%0,%1,%2,%3}, {%4,%5,%6,%7}, {%8,%9}, {%0,%1,%2,%3};"
                    : "+f"(acc[nt][0]), "+f"(acc[nt][1]), "+f"(acc[nt][2]), "+f"(acc[nt][3])
                    : "r"(a0), "r"(a1), "r"(a2), "r"(a3), "r"(bb.x), "r"(bb.y));
            }
        }
        // commit next tile to the other buffer (readers of it finished before
        // the sync at the end of the previous iteration)
        if (it + 1 < DIN / AKC) {
            __half* An = As + ((it + 1) & 1) * AS_TILE;
#pragma unroll
            for (int i = 0; i < 8; i++) {
                int r = i * 16 + pr_r0;
                uint2 pk;
                *reinterpret_cast<__half2*>(&pk.x) = __floats2half2_rn(pref[i].x, pref[i].y);
                *reinterpret_cast<__half2*>(&pk.y) = __floats2half2_rn(pref[i].z, pref[i].w);
                *(uint2*)&An[r * APAD + pr_c4 * 4] = pk;
            }
        }
        __syncthreads();
    }

    int row_lo = row0 + w * 16 + g;
    int row_hi = row_lo + 8;
#pragma unroll
    for (int nt = 0; nt < 8; nt++) {
        int c0 = nt * 8 + 2 * q, c1 = c0 + 1;
        if (row_lo < N_NODES)
            *(__half2*)&g_Hh[(size_t)row_lo * 64 + c0] = __floats2half2_rn(acc[nt][0], acc[nt][1]);
        if (row_hi < N_NODES)
            *(__half2*)&g_Hh[(size_t)row_hi * 64 + c0] = __floats2half2_rn(acc[nt][2], acc[nt][3]);
        float ad0 = adst[c0], ad1 = adst[c1];
        float psl_d = acc[nt][0] * ad0 + acc[nt][1] * ad1;
        float psh_d = acc[nt][2] * ad0 + acc[nt][3] * ad1;
        psl_d += __shfl_xor_sync(0xffffffffu, psl_d, 1);
        psl_d += __shfl_xor_sync(0xffffffffu, psl_d, 2);
        psh_d += __shfl_xor_sync(0xffffffffu, psh_d, 1);
        psh_d += __shfl_xor_sync(0xffffffffu, psh_d, 2);
        if (q == 0) {
            if (row_lo < N_NODES) g_ald[row_lo * 8 + nt] = psl_d;
            if (row_hi < N_NODES) g_ald[row_hi * 8 + nt] = psh_d;
        }
    }
}

// ---------------- layer 1: 8 lanes/node, lane = layer, 2-edge unrolled ----------
__global__ __launch_bounds__(256) void k_edge1v(const float* __restrict__ asrc,
                                                const float* __restrict__ bias_h,
                                                const float* __restrict__ Wout,
                                                const float* __restrict__ aso,
                                                const float* __restrict__ ado) {
    int tid = blockIdx.x * blockDim.x + threadIdx.x;
    int n = tid >> 3;
    int lj = tid & 7;

    float aldj = g_ald[n * 8 + lj];
    float as[8];
#pragma unroll
    for (int f = 0; f < 8; f++) as[f] = asrc[lj * 8 + f];

    float acc[8];
#pragma unroll
    for (int f = 0; f < 8; f++) acc[f] = 0.f;
    float sum = 0.f;

    int p0 = g_off[n], p1 = g_off[n + 1];
    int p = p0;
    for (; p + 2 <= p1; p += 2) {
        int s0 = __ldg(&g_esrc[p]);
        int s1 = __ldg(&g_esrc[p + 1]);
        uint4 ha = *(const uint4*)&g_Hh[(size_t)s0 * 64 + lj * 8];
        uint4 hb = *(const uint4*)&g_Hh[(size_t)s1 * 64 + lj * 8];
        float2 a0 = h2f2(ha.x), a1 = h2f2(ha.y), a2 = h2f2(ha.z), a3 = h2f2(ha.w);
        float2 b0 = h2f2(hb.x), b1 = h2f2(hb.y), b2 = h2f2(hb.z), b3 = h2f2(hb.w);
        float alsa = a0.x * as[0] + a0.y * as[1] + a1.x * as[2] + a1.y * as[3]
                   + a2.x * as[4] + a2.y * as[5] + a3.x * as[6] + a3.y * as[7];
        float alsb = b0.x * as[0] + b0.y * as[1] + b1.x * as[2] + b1.y * as[3]
                   + b2.x * as[4] + b2.y * as[5] + b3.x * as[6] + b3.y * as[7];
        float eva = alsa + aldj; eva = (eva > 0.f) ? eva : NEG_SLOPE * eva;
        float evb = alsb + aldj; evb = (evb > 0.f) ? evb : NEG_SLOPE * evb;
        float wa = __expf(eva), wb = __expf(evb);
        sum += wa + wb;
        acc[0] = fmaf(wa, a0.x, fmaf(wb, b0.x, acc[0]));
        acc[1] = fmaf(wa, a0.y, fmaf(wb, b0.y, acc[1]));
        acc[2] = fmaf(wa, a1.x, fmaf(wb, b1.x, acc[2]));
        acc[3] = fmaf(wa, a1.y, fmaf(wb, b1.y, acc[3]));
        acc[4] = fmaf(wa, a2.x, fmaf(wb, b2.x, acc[4]));
        acc[5] = fmaf(wa, a2.y, fmaf(wb, b2.y, acc[5]));
        acc[6] = fmaf(wa, a3.x, fmaf(wb, b3.x, acc[6]));
        acc[7] = fmaf(wa, a3.y, fmaf(wb, b3.y, acc[7]));
    }
    if (p < p1) {
        int s = __ldg(&g_esrc[p]);
        uint4 h = *(const uint4*)&g_Hh[(size_t)s * 64 + lj * 8];
        float2 f0 = h2f2(h.x), f1 = h2f2(h.y), f2 = h2f2(h.z), f3 = h2f2(h.w);
        float als = f0.x * as[0] + f0.y * as[1] + f1.x * as[2] + f1.y * as[3]
                  + f2.x * as[4] + f2.y * as[5] + f3.x * as[6] + f3.y * as[7];
        float ev = als + aldj;
        ev = (ev > 0.f) ? ev : NEG_SLOPE * ev;
        float wv = __expf(ev);
        sum += wv;
        acc[0] = fmaf(wv, f0.x, acc[0]);
        acc[1] = fmaf(wv, f0.y, acc[1]);
        acc[2] = fmaf(wv, f1.x, acc[2]);
        acc[3] = fmaf(wv, f1.y, acc[3]);
        acc[4] = fmaf(wv, f2.x, acc[4]);
        acc[5] = fmaf(wv, f2.y, acc[5]);
        acc[6] = fmaf(wv, f3.x, acc[6]);
        acc[7] = fmaf(wv, f3.y, acc[7]);
    }

    float r = 1.f / sum;
    float tot[8];
#pragma unroll
    for (int f = 0; f < 8; f++) tot[f] = acc[f] * r + bias_h[lj * 8 + f];
#pragma unroll
    for (int o = 1; o < 8; o <<= 1)
#pragma unroll
        for (int f = 0; f < 8; f++)
            tot[f] += __shfl_xor_sync(0xffffffffu, tot[f], o);

    float h2[8];
#pragma unroll
    for (int f = 0; f < 8; f++) {
        float v = tot[f] * 0.125f;
        h2[f] = (v > 0.f) ? v : (__expf(v) - 1.f);
    }
    float c0 = 0.f, c1 = 0.f;
#pragma unroll
    for (int f = 0; f < 8; f++) {
        c0 = fmaf(h2[f], Wout[f * 16 + lj], c0);
        c1 = fmaf(h2[f], Wout[f * 16 + lj + 8], c1);
    }
    g_h3h[(size_t)n * 16 + lj]     = __float2half(c0);
    g_h3h[(size_t)n * 16 + lj + 8] = __float2half(c1);

    float ss = c0 * aso[lj] + c1 * aso[lj + 8];
    float dd = c0 * ado[lj] + c1 * ado[lj + 8];
#pragma unroll
    for (int o = 1; o < 8; o <<= 1) {
        ss += __shfl_xor_sync(0xffffffffu, ss, o);
        dd += __shfl_xor_sync(0xffffffffu, dd, o);
    }
    if (lj == 0) {
        g_al2s[n] = ss;
        g_al2d[n] = dd;
    }
}

// ---------------- layer 2: 4 lanes/node, lane = feature-quad, 2-edge unrolled ---
__global__ __launch_bounds__(128) void k_edge2v(const float* __restrict__ bias_o,
                                                float* __restrict__ out) {
    int tid = blockIdx.x * blockDim.x + threadIdx.x;
    int n = tid >> 2;
    int q4 = tid & 3;

    float al2d = g_al2d[n];

    float acc[4] = {0.f, 0.f, 0.f, 0.f};
    float sum = 0.f;

    int p0 = g_off[n], p1 = g_off[n + 1];
    int p = p0;
    for (; p + 2 <= p1; p += 2) {
        int s0 = __ldg(&g_esrc[p]);
        int s1 = __ldg(&g_esrc[p + 1]);
        float la = g_al2s[s0];
        float lb = g_al2s[s1];
        uint2 ha = *(const uint2*)&g_h3h[(size_t)s0 * 16 + q4 * 4];
        uint2 hb = *(const uint2*)&g_h3h[(size_t)s1 * 16 + q4 * 4];
        float ta = la + al2d; ta = (ta > 0.f) ? ta : NEG_SLOPE * ta;
        float tb = lb + al2d; tb = (tb > 0.f) ? tb : NEG_SLOPE * tb;
        float wa = __expf(ta), wb = __expf(tb);
        sum += wa + wb;
        float2 a0 = h2f2(ha.x), a1 = h2f2(ha.y);
        float2 b0 = h2f2(hb.x), b1 = h2f2(hb.y);
        acc[0] = fmaf(wa, a0.x, fmaf(wb, b0.x, acc[0]));
        acc[1] = fmaf(wa, a0.y, fmaf(wb, b0.y, acc[1]));
        acc[2] = fmaf(wa, a1.x, fmaf(wb, b1.x, acc[2]));
        acc[3] = fmaf(wa, a1.y, fmaf(wb, b1.y, acc[3]));
    }
    if (p < p1) {
        int s = __ldg(&g_esrc[p]);
        float l2 = g_al2s[s];
        uint2 h = *(const uint2*)&g_h3h[(size_t)s * 16 + q4 * 4];
        float tv = l2 + al2d;
        tv = (tv > 0.f) ? tv : NEG_SLOPE * tv;
        float wv = __expf(tv);
        sum += wv;
        float2 f0 = h2f2(h.x), f1 = h2f2(h.y);
        acc[0] = fmaf(wv, f0.x, acc[0]);
        acc[1] = fmaf(wv, f0.y, acc[1]);
        acc[2] = fmaf(wv, f1.x, acc[2]);
        acc[3] = fmaf(wv, f1.y, acc[3]);
    }

    float rs = 1.f / sum;
    float o4[4];
#pragma unroll
    for (int c = 0; c < 4; c++) o4[c] = acc[c] * rs + bias_o[q4 * 4 + c];

    float m = fmaxf(fmaxf(o4[0], o4[1]), fmaxf(o4[2], o4[3]));
    m = fmaxf(m, __shfl_xor_sync(0xffffffffu, m, 1));
    m = fmaxf(m, __shfl_xor_sync(0xffffffffu, m, 2));
    float se = __expf(o4[0] - m) + __expf(o4[1] - m) + __expf(o4[2] - m) + __expf(o4[3] - m);
    se += __shfl_xor_sync(0xffffffffu, se, 1);
    se += __shfl_xor_sync(0xffffffffu, se, 2);
    float lse = __logf(se);
    *(float4*)&out[(size_t)n * 16 + q4 * 4] =
        make_float4(o4[0] - m - lse, o4[1] - m - lse, o4[2] - m - lse, o4[3] - m - lse);
}

// ---------------- launch ---------------------------------------------------------
#define GEMM_SMEM (2 * AS_TILE * 2 + 64 * WT_K * 2)

extern "C" void kernel_launch(void* const* d_in, const int* in_sizes, int n_in,
                              void* d_out, int out_size) {
    const float* x    = (const float*)d_in[0];
    const void*  ei   = d_in[1];
    const float* Wh   = (const float*)d_in[2];
    const float* asrc = (const float*)d_in[3];
    const float* adst = (const float*)d_in[4];
    const float* bh   = (const float*)d_in[5];
    const float* Wout = (const float*)d_in[6];
    const float* aso  = (const float*)d_in[7];
    const float* ado  = (const float*)d_in[8];
    const float* bo   = (const float*)d_in[9];
    float*       out  = (float*)d_out;

    static int smem_set = 0;
    if (!smem_set) {
        cudaFuncSetAttribute(k_gemm, cudaFuncAttributeMaxDynamicSharedMemorySize, GEMM_SMEM);
        smem_set = 1;
    }

    cudaStream_t s2;
    cudaStreamCreateWithFlags(&s2, cudaStreamNonBlocking);
    cudaEvent_t evA, evB;
    cudaEventCreateWithFlags(&evA, cudaEventDisableTiming);
    cudaEventCreateWithFlags(&evB, cudaEventDisableTiming);

    cudaEventRecord(evA, 0);
    cudaStreamWaitEvent(s2, evA, 0);

    // Submission order keeps k_gemm as the 5th counted launch (ncu -s lands there).
    void* p_deg;
    cudaGetSymbolAddress(&p_deg, g_deg);
    cudaMemsetAsync(p_deg, 0, sizeof(int) * (N_NODES + NPART), s2);   // 1
    k_count<<<(ET + 255) / 256, 256, 0, s2>>>(ei);                     // 2
    k_scan<<<NPART, 1024, 0, s2>>>();                                  // 3
    k_prep_w<<<(64 * DIN + 255) / 256, 256>>>(Wh);                     // 4 (main)
    k_gemm<<<(N_NODES + GROWS - 1) / GROWS, 256, GEMM_SMEM>>>(x, adst);// 5 (main)
    k_scatter<<<(ET + 255) / 256, 256, 0, s2>>>(ei);                   // 6 (s2)
    cudaEventRecord(evB, s2);

    cudaStreamWaitEvent(0, evB, 0);
    k_edge1v<<<(N_NODES * 8) / 256, 256>>>(asrc, bh, Wout, aso, ado);  // 7
    k_edge2v<<<(N_NODES * 4) / 128, 128>>>(bo, out);                   // 8
}

// round 14
// speedup vs baseline: 1.1543x; 1.1543x over previous
#include <cuda_runtime.h>
#include <cuda_fp16.h>
#include <math.h>

#define N_NODES 100000
#define DIN     512
#define NE      1600000
#define ET      (NE + N_NODES)   // edges + self loops
#define NEG_SLOPE 0.2f
#define NPART   ((N_NODES + 1023) / 1024)
#define WT_K    520              // padded k stride

// ---------------- scratch (device globals) -------------------------------------
__device__ __align__(128) __half g_Wt[64 * WT_K];              // W^T as half [n][k]
__device__ __align__(128) __half g_Hh[(size_t)N_NODES * 64];   // fp16 messages L1
__device__ __align__(128) float  g_ald[N_NODES * 8];
__device__ __align__(128) __half g_h3h[(size_t)N_NODES * 16];  // fp16 messages L2
__device__ __align__(128) float  g_al2s[N_NODES];
__device__ __align__(128) float  g_al2d[N_NODES];
__device__ int g_esrc[ET];
__device__ int g_deg[N_NODES + NPART];
__device__ int g_off[N_NODES + 1];
__device__ int g_cur[N_NODES];

__device__ __forceinline__ float2 h2f2(unsigned u) {
    __half2 h = *reinterpret_cast<const __half2*>(&u);
    return __half22float2(h);
}

__device__ __forceinline__ int detect_is64(const int* ei32) {
    int allzero = 1;
#pragma unroll 8
    for (int i = 0; i < 64; i++)
        if (__ldg(&ei32[2 * i + 1]) != 0) { allzero = 0; break; }
    return allzero;
}

__device__ __forceinline__ void decode_edge(const void* ei, int is64, int e,
                                            int* s, int* d) {
    if (e < NE) {
        int sv, dv;
        if (is64) {
            const long long* p = (const long long*)ei;
            sv = (int)p[e];
            dv = (int)p[(size_t)NE + e];
        } else {
            const int* p = (const int*)ei;
            sv = p[e];
            dv = p[NE + e];
        }
        *s = min(max(sv, 0), N_NODES - 1);
        *d = min(max(dv, 0), N_NODES - 1);
    } else {
        *s = e - NE;
        *d = e - NE;
    }
}

__global__ void k_count(const void* __restrict__ ei) {
    int is64 = detect_is64((const int*)ei);
    int e = blockIdx.x * blockDim.x + threadIdx.x;
    if (e >= ET) return;
    int s, d;
    decode_edge(ei, is64, e, &s, &d);
    atomicAdd(&g_deg[d], 1);
}

__global__ __launch_bounds__(1024) void k_scan() {
    __shared__ int wsum[32];
    __shared__ int sbase;
    int t = threadIdx.x, b = blockIdx.x;
    if (t == 0) sbase = 0;
    int i = b * 1024 + t;
    int v = (i < N_NODES) ? g_deg[i] : 0;
    int x = v;
    int lane = t & 31, w = t >> 5;
#pragma unroll
    for (int o = 1; o < 32; o <<= 1) {
        int y = __shfl_up_sync(0xffffffffu, x, o);
        if (lane >= o) x += y;
    }
    if (lane == 31) wsum[w] = x;
    __syncthreads();
    if (t < 32) {
        int y = wsum[t];
#pragma unroll
        for (int o = 1; o < 32; o <<= 1) {
            int z = __shfl_up_sync(0xffffffffu, y, o);
            if (t >= o) y += z;
        }
        wsum[t] = y;
    }
    __syncthreads();

    volatile int* bs = (volatile int*)&g_deg[N_NODES];
    if (t == 0) bs[b] = wsum[31] + 1;
    if (t < b) {
        int pv;
        while ((pv = bs[t]) == 0) {}
        atomicAdd(&sbase, pv - 1);
    }
    __syncthreads();

    int excl = x - v + (w > 0 ? wsum[w - 1] : 0) + sbase;
    if (i < N_NODES) { g_off[i] = excl; g_cur[i] = excl; }
    if (b == 0 && t == 0) g_off[N_NODES] = ET;
}

__global__ void k_scatter(const void* __restrict__ ei) {
    int is64 = detect_is64((const int*)ei);
    int e = blockIdx.x * blockDim.x + threadIdx.x;
    if (e >= ET) return;
    int s, d;
    decode_edge(ei, is64, e, &s, &d);
    int pos = atomicAdd(&g_cur[d], 1);
    g_esrc[pos] = s;
}

// g_Wt[n][k] = (half) W_hidden[n/8][k][n%8]   (unpacked layout: conflict-free LDS.32)
__global__ void k_prep_w(const float* __restrict__ Wh) {
    int i = blockIdx.x * blockDim.x + threadIdx.x;
    if (i >= 64 * DIN) return;
    int n = i >> 9, k = i & 511;
    int l = n >> 3, f = n & 7;
    g_Wt[n * WT_K + k] = __float2half(Wh[(size_t)l * (DIN * 8) + k * 8 + f]);
}

// ---------------- tensor-core GEMM (R12 proven version: 50.3 us) ----------------
// Software-pipelined: next x tile prefetched into registers right after the sync.
// x via __ldcs (single-use stream; keep g_Hh resident in L2).
#define GROWS 128
#define AKC   64
#define APAD  72
__global__ __launch_bounds__(256) void k_gemm(const float* __restrict__ x,
                                              const float* __restrict__ adst) {
    extern __shared__ char smem[];
    __half* As = (__half*)smem;                       // [128][72]
    __half* Ws = (__half*)(smem + GROWS * APAD * 2);  // [64][520]

    const int t = threadIdx.x;
    const int w = t >> 5;
    const int l = t & 31;
    const int row0 = blockIdx.x * GROWS;
    const int g = l >> 2;
    const int q = l & 3;

    {
        const uint4* src = (const uint4*)g_Wt;
#pragma unroll
        for (int i = 0; i < 16; i++) {
            int idx = i * 256 + t;
            int r = idx >> 6, c = idx & 63;
            *(uint4*)&Ws[r * WT_K + c * 8] = src[(r * WT_K + c * 8) >> 3];
        }
    }

    float acc[8][4];
#pragma unroll
    for (int n = 0; n < 8; n++)
#pragma unroll
        for (int j = 0; j < 4; j++) acc[n][j] = 0.f;

    const int arow = (l & 7) + ((l & 8) ? 8 : 0);
    const int acol = (l & 16) ? 8 : 0;

    const int pr_c4 = t & 15;
    const int pr_r0 = t >> 4;
    float4 pref[8];

#pragma unroll
    for (int i = 0; i < 8; i++) {
        int r = i * 16 + pr_r0;
        int rg = row0 + r; if (rg >= N_NODES) rg = N_NODES - 1;
        pref[i] = __ldcs((const float4*)&x[(size_t)rg * DIN + pr_c4 * 4]);
    }

    __syncthreads();   // Ws ready

    for (int kt = 0; kt < DIN; kt += AKC) {
#pragma unroll
        for (int i = 0; i < 8; i++) {
            int r = i * 16 + pr_r0;
            __half2* dst = (__half2*)&As[r * APAD + pr_c4 * 4];
            dst[0] = __floats2half2_rn(pref[i].x, pref[i].y);
            dst[1] = __floats2half2_rn(pref[i].z, pref[i].w);
        }
        __syncthreads();

        if (kt + AKC < DIN) {
#pragma unroll
            for (int i = 0; i < 8; i++) {
                int r = i * 16 + pr_r0;
                int rg = row0 + r; if (rg >= N_NODES) rg = N_NODES - 1;
                pref[i] = __ldcs((const float4*)&x[(size_t)rg * DIN + kt + AKC + pr_c4 * 4]);
            }
        }

#pragma unroll
        for (int k0 = 0; k0 < AKC; k0 += 16) {
            unsigned a0, a1, a2, a3;
            unsigned aaddr = __cvta_generic_to_shared(
                &As[(w * 16 + arow) * APAD + k0 + acol]);
            asm volatile("ldmatrix.sync.aligned.m8n8.x4.shared.b16 {%0,%1,%2,%3}, [%4];"
                         : "=r"(a0), "=r"(a1), "=r"(a2), "=r"(a3) : "r"(aaddr));
            int kg = kt + k0;
#pragma unroll
            for (int nt = 0; nt < 8; nt++) {
                int n = nt * 8 + g;
                unsigned b0 = *(const unsigned*)&Ws[n * WT_K + kg + 2 * q];
                unsigned b1 = *(const unsigned*)&Ws[n * WT_K + kg + 8 + 2 * q];
                asm volatile(
                    "mma.sync.aligned.m16n8k16.row.col.f32.f16.f16.f32 "
                    "{%0,%1,%2,%3}, {%4,%5,%6,%7}, {%8,%9}, {%0,%1,%2,%3};"
                    : "+f"(acc[nt][0]), "+f"(acc[nt][1]), "+f"(acc[nt][2]), "+f"(acc[nt][3])
                    : "r"(a0), "r"(a1), "r"(a2), "r"(a3), "r"(b0), "r"(b1));
            }
        }
        __syncthreads();
    }

    int row_lo = row0 + w * 16 + g;
    int row_hi = row_lo + 8;
#pragma unroll
    for (int nt = 0; nt < 8; nt++) {
        int c0 = nt * 8 + 2 * q, c1 = c0 + 1;
        if (row_lo < N_NODES)
            *(__half2*)&g_Hh[(size_t)row_lo * 64 + c0] = __floats2half2_rn(acc[nt][0], acc[nt][1]);
        if (row_hi < N_NODES)
            *(__half2*)&g_Hh[(size_t)row_hi * 64 + c0] = __floats2half2_rn(acc[nt][2], acc[nt][3]);
        float ad0 = adst[c0], ad1 = adst[c1];
        float psl_d = acc[nt][0] * ad0 + acc[nt][1] * ad1;
        float psh_d = acc[nt][2] * ad0 + acc[nt][3] * ad1;
        psl_d += __shfl_xor_sync(0xffffffffu, psl_d, 1);
        psl_d += __shfl_xor_sync(0xffffffffu, psl_d, 2);
        psh_d += __shfl_xor_sync(0xffffffffu, psh_d, 1);
        psh_d += __shfl_xor_sync(0xffffffffu, psh_d, 2);
        if (q == 0) {
            if (row_lo < N_NODES) g_ald[row_lo * 8 + nt] = psl_d;
            if (row_hi < N_NODES) g_ald[row_hi * 8 + nt] = psh_d;
        }
    }
}

// ---------------- layer 1: 8 lanes/node, lane = layer, 2-edge unrolled ----------
__global__ __launch_bounds__(256) void k_edge1v(const float* __restrict__ asrc,
                                                const float* __restrict__ bias_h,
                                                const float* __restrict__ Wout,
                                                const float* __restrict__ aso,
                                                const float* __restrict__ ado) {
    int tid = blockIdx.x * blockDim.x + threadIdx.x;
    int n = tid >> 3;
    int lj = tid & 7;

    float aldj = g_ald[n * 8 + lj];
    float as[8];
#pragma unroll
    for (int f = 0; f < 8; f++) as[f] = asrc[lj * 8 + f];

    float acc[8];
#pragma unroll
    for (int f = 0; f < 8; f++) acc[f] = 0.f;
    float sum = 0.f;

    int p0 = g_off[n], p1 = g_off[n + 1];
    int p = p0;
    for (; p + 2 <= p1; p += 2) {
        int s0 = __ldg(&g_esrc[p]);
        int s1 = __ldg(&g_esrc[p + 1]);
        uint4 ha = *(const uint4*)&g_Hh[(size_t)s0 * 64 + lj * 8];
        uint4 hb = *(const uint4*)&g_Hh[(size_t)s1 * 64 + lj * 8];
        float2 a0 = h2f2(ha.x), a1 = h2f2(ha.y), a2 = h2f2(ha.z), a3 = h2f2(ha.w);
        float2 b0 = h2f2(hb.x), b1 = h2f2(hb.y), b2 = h2f2(hb.z), b3 = h2f2(hb.w);
        float alsa = a0.x * as[0] + a0.y * as[1] + a1.x * as[2] + a1.y * as[3]
                   + a2.x * as[4] + a2.y * as[5] + a3.x * as[6] + a3.y * as[7];
        float alsb = b0.x * as[0] + b0.y * as[1] + b1.x * as[2] + b1.y * as[3]
                   + b2.x * as[4] + b2.y * as[5] + b3.x * as[6] + b3.y * as[7];
        float eva = alsa + aldj; eva = (eva > 0.f) ? eva : NEG_SLOPE * eva;
        float evb = alsb + aldj; evb = (evb > 0.f) ? evb : NEG_SLOPE * evb;
        float wa = __expf(eva), wb = __expf(evb);
        sum += wa + wb;
        acc[0] = fmaf(wa, a0.x, fmaf(wb, b0.x, acc[0]));
        acc[1] = fmaf(wa, a0.y, fmaf(wb, b0.y, acc[1]));
        acc[2] = fmaf(wa, a1.x, fmaf(wb, b1.x, acc[2]));
        acc[3] = fmaf(wa, a1.y, fmaf(wb, b1.y, acc[3]));
        acc[4] = fmaf(wa, a2.x, fmaf(wb, b2.x, acc[4]));
        acc[5] = fmaf(wa, a2.y, fmaf(wb, b2.y, acc[5]));
        acc[6] = fmaf(wa, a3.x, fmaf(wb, b3.x, acc[6]));
        acc[7] = fmaf(wa, a3.y, fmaf(wb, b3.y, acc[7]));
    }
    if (p < p1) {
        int s = __ldg(&g_esrc[p]);
        uint4 h = *(const uint4*)&g_Hh[(size_t)s * 64 + lj * 8];
        float2 f0 = h2f2(h.x), f1 = h2f2(h.y), f2 = h2f2(h.z), f3 = h2f2(h.w);
        float als = f0.x * as[0] + f0.y * as[1] + f1.x * as[2] + f1.y * as[3]
                  + f2.x * as[4] + f2.y * as[5] + f3.x * as[6] + f3.y * as[7];
        float ev = als + aldj;
        ev = (ev > 0.f) ? ev : NEG_SLOPE * ev;
        float wv = __expf(ev);
        sum += wv;
        acc[0] = fmaf(wv, f0.x, acc[0]);
        acc[1] = fmaf(wv, f0.y, acc[1]);
        acc[2] = fmaf(wv, f1.x, acc[2]);
        acc[3] = fmaf(wv, f1.y, acc[3]);
        acc[4] = fmaf(wv, f2.x, acc[4]);
        acc[5] = fmaf(wv, f2.y, acc[5]);
        acc[6] = fmaf(wv, f3.x, acc[6]);
        acc[7] = fmaf(wv, f3.y, acc[7]);
    }

    float r = 1.f / sum;
    float tot[8];
#pragma unroll
    for (int f = 0; f < 8; f++) tot[f] = acc[f] * r + bias_h[lj * 8 + f];
#pragma unroll
    for (int o = 1; o < 8; o <<= 1)
#pragma unroll
        for (int f = 0; f < 8; f++)
            tot[f] += __shfl_xor_sync(0xffffffffu, tot[f], o);

    float h2[8];
#pragma unroll
    for (int f = 0; f < 8; f++) {
        float v = tot[f] * 0.125f;
        h2[f] = (v > 0.f) ? v : (__expf(v) - 1.f);
    }
    float c0 = 0.f, c1 = 0.f;
#pragma unroll
    for (int f = 0; f < 8; f++) {
        c0 = fmaf(h2[f], Wout[f * 16 + lj], c0);
        c1 = fmaf(h2[f], Wout[f * 16 + lj + 8], c1);
    }
    g_h3h[(size_t)n * 16 + lj]     = __float2half(c0);
    g_h3h[(size_t)n * 16 + lj + 8] = __float2half(c1);

    float ss = c0 * aso[lj] + c1 * aso[lj + 8];
    float dd = c0 * ado[lj] + c1 * ado[lj + 8];
#pragma unroll
    for (int o = 1; o < 8; o <<= 1) {
        ss += __shfl_xor_sync(0xffffffffu, ss, o);
        dd += __shfl_xor_sync(0xffffffffu, dd, o);
    }
    if (lj == 0) {
        g_al2s[n] = ss;
        g_al2d[n] = dd;
    }
}

// ---------------- layer 2: 4 lanes/node, lane = feature-quad, 2-edge unrolled ---
__global__ __launch_bounds__(128) void k_edge2v(const float* __restrict__ bias_o,
                                                float* __restrict__ out) {
    int tid = blockIdx.x * blockDim.x + threadIdx.x;
    int n = tid >> 2;
    int q4 = tid & 3;

    float al2d = g_al2d[n];

    float acc[4] = {0.f, 0.f, 0.f, 0.f};
    float sum = 0.f;

    int p0 = g_off[n], p1 = g_off[n + 1];
    int p = p0;
    for (; p + 2 <= p1; p += 2) {
        int s0 = __ldg(&g_esrc[p]);
        int s1 = __ldg(&g_esrc[p + 1]);
        float la = g_al2s[s0];
        float lb = g_al2s[s1];
        uint2 ha = *(const uint2*)&g_h3h[(size_t)s0 * 16 + q4 * 4];
        uint2 hb = *(const uint2*)&g_h3h[(size_t)s1 * 16 + q4 * 4];
        float ta = la + al2d; ta = (ta > 0.f) ? ta : NEG_SLOPE * ta;
        float tb = lb + al2d; tb = (tb > 0.f) ? tb : NEG_SLOPE * tb;
        float wa = __expf(ta), wb = __expf(tb);
        sum += wa + wb;
        float2 a0 = h2f2(ha.x), a1 = h2f2(ha.y);
        float2 b0 = h2f2(hb.x), b1 = h2f2(hb.y);
        acc[0] = fmaf(wa, a0.x, fmaf(wb, b0.x, acc[0]));
        acc[1] = fmaf(wa, a0.y, fmaf(wb, b0.y, acc[1]));
        acc[2] = fmaf(wa, a1.x, fmaf(wb, b1.x, acc[2]));
        acc[3] = fmaf(wa, a1.y, fmaf(wb, b1.y, acc[3]));
    }
    if (p < p1) {
        int s = __ldg(&g_esrc[p]);
        float l2 = g_al2s[s];
        uint2 h = *(const uint2*)&g_h3h[(size_t)s * 16 + q4 * 4];
        float tv = l2 + al2d;
        tv = (tv > 0.f) ? tv : NEG_SLOPE * tv;
        float wv = __expf(tv);
        sum += wv;
        float2 f0 = h2f2(h.x), f1 = h2f2(h.y);
        acc[0] = fmaf(wv, f0.x, acc[0]);
        acc[1] = fmaf(wv, f0.y, acc[1]);
        acc[2] = fmaf(wv, f1.x, acc[2]);
        acc[3] = fmaf(wv, f1.y, acc[3]);
    }

    float rs = 1.f / sum;
    float o4[4];
#pragma unroll
    for (int c = 0; c < 4; c++) o4[c] = acc[c] * rs + bias_o[q4 * 4 + c];

    float m = fmaxf(fmaxf(o4[0], o4[1]), fmaxf(o4[2], o4[3]));
    m = fmaxf(m, __shfl_xor_sync(0xffffffffu, m, 1));
    m = fmaxf(m, __shfl_xor_sync(0xffffffffu, m, 2));
    float se = __expf(o4[0] - m) + __expf(o4[1] - m) + __expf(o4[2] - m) + __expf(o4[3] - m);
    se += __shfl_xor_sync(0xffffffffu, se, 1);
    se += __shfl_xor_sync(0xffffffffu, se, 2);
    float lse = __logf(se);
    *(float4*)&out[(size_t)n * 16 + q4 * 4] =
        make_float4(o4[0] - m - lse, o4[1] - m - lse, o4[2] - m - lse, o4[3] - m - lse);
}

// ---------------- launch ---------------------------------------------------------
#define GEMM_SMEM (GROWS * APAD * 2 + 64 * WT_K * 2)

extern "C" void kernel_launch(void* const* d_in, const int* in_sizes, int n_in,
                              void* d_out, int out_size) {
    const float* x    = (const float*)d_in[0];
    const void*  ei   = d_in[1];
    const float* Wh   = (const float*)d_in[2];
    const float* asrc = (const float*)d_in[3];
    const float* adst = (const float*)d_in[4];
    const float* bh   = (const float*)d_in[5];
    const float* Wout = (const float*)d_in[6];
    const float* aso  = (const float*)d_in[7];
    const float* ado  = (const float*)d_in[8];
    const float* bo   = (const float*)d_in[9];
    float*       out  = (float*)d_out;

    static int smem_set = 0;
    if (!smem_set) {
        cudaFuncSetAttribute(k_gemm, cudaFuncAttributeMaxDynamicSharedMemorySize, GEMM_SMEM);
        smem_set = 1;
    }

    cudaStream_t s2;
    cudaStreamCreateWithFlags(&s2, cudaStreamNonBlocking);
    cudaEvent_t evA, evB;
    cudaEventCreateWithFlags(&evA, cudaEventDisableTiming);
    cudaEventCreateWithFlags(&evB, cudaEventDisableTiming);

    cudaEventRecord(evA, 0);
    cudaStreamWaitEvent(s2, evA, 0);

    // Submission order keeps k_gemm as the 5th counted launch (ncu -s lands there).
    void* p_deg;
    cudaGetSymbolAddress(&p_deg, g_deg);
    cudaMemsetAsync(p_deg, 0, sizeof(int) * (N_NODES + NPART), s2);   // 1
    k_count<<<(ET + 255) / 256, 256, 0, s2>>>(ei);                     // 2
    k_scan<<<NPART, 1024, 0, s2>>>();                                  // 3
    k_prep_w<<<(64 * DIN + 255) / 256, 256>>>(Wh);                     // 4 (main)
    k_gemm<<<(N_NODES + GROWS - 1) / GROWS, 256, GEMM_SMEM>>>(x, adst);// 5 (main)
    k_scatter<<<(ET + 255) / 256, 256, 0, s2>>>(ei);                   // 6 (s2)
    cudaEventRecord(evB, s2);

    cudaStreamWaitEvent(0, evB, 0);
    k_edge1v<<<(N_NODES * 8) / 256, 256>>>(asrc, bh, Wout, aso, ado);  // 7
    k_edge2v<<<(N_NODES * 4) / 128, 128>>>(bo, out);                   // 8
}

// round 15
// speedup vs baseline: 1.1700x; 1.0136x over previous
#include <cuda_runtime.h>
#include <cuda_fp16.h>
#include <math.h>

#define N_NODES 100000
#define DIN     512
#define NE      1600000
#define ET      (NE + N_NODES)   // edges + self loops
#define NEG_SLOPE 0.2f
#define WT_K    520              // padded k stride
#define SLOT_CAP 128             // per-node bucket capacity (P(deg>=128) ~ 1e-63)

// ---------------- scratch (device globals) -------------------------------------
__device__ __align__(128) __half g_Wt[64 * WT_K];              // W^T as half [n][k]
__device__ __align__(128) __half g_Hh[(size_t)N_NODES * 64];   // fp16 messages L1
__device__ __align__(128) float  g_ald[N_NODES * 8];
__device__ __align__(128) __half g_h3h[(size_t)N_NODES * 16];  // fp16 messages L2
__device__ __align__(128) float  g_al2s[N_NODES];
__device__ __align__(128) float  g_al2d[N_NODES];
__device__ int g_slots[(size_t)N_NODES * SLOT_CAP];            // bucket CSR
__device__ int g_cnt[N_NODES];

__device__ __forceinline__ float2 h2f2(unsigned u) {
    __half2 h = *reinterpret_cast<const __half2*>(&u);
    return __half22float2(h);
}

// Per-block edge-index dtype detection (JAX x64-off downcast)
__device__ __forceinline__ int detect_is64(const int* ei32) {
    int allzero = 1;
#pragma unroll 8
    for (int i = 0; i < 64; i++)
        if (__ldg(&ei32[2 * i + 1]) != 0) { allzero = 0; break; }
    return allzero;
}

__device__ __forceinline__ void decode_edge(const void* ei, int is64, int e,
                                            int* s, int* d) {
    if (e < NE) {
        int sv, dv;
        if (is64) {
            const long long* p = (const long long*)ei;
            sv = (int)p[e];
            dv = (int)p[(size_t)NE + e];
        } else {
            const int* p = (const int*)ei;
            sv = p[e];
            dv = p[NE + e];
        }
        *s = min(max(sv, 0), N_NODES - 1);
        *d = min(max(dv, 0), N_NODES - 1);
    } else {
        *s = e - NE;
        *d = e - NE;
    }
}

// ---------------- single-pass bucket scatter (no count, no scan) ----------------
__global__ void k_scatter(const void* __restrict__ ei) {
    int is64 = detect_is64((const int*)ei);
    int e = blockIdx.x * blockDim.x + threadIdx.x;
    if (e >= ET) return;
    int s, d;
    decode_edge(ei, is64, e, &s, &d);
    int pos = atomicAdd(&g_cnt[d], 1);
    if (pos < SLOT_CAP)                       // overflow guard (never fires statistically)
        g_slots[(size_t)d * SLOT_CAP + pos] = s;
}

// g_Wt[n][k] = (half) W_hidden[n/8][k][n%8]   (unpacked: conflict-free LDS.32)
__global__ void k_prep_w(const float* __restrict__ Wh) {
    int i = blockIdx.x * blockDim.x + threadIdx.x;
    if (i >= 64 * DIN) return;
    int n = i >> 9, k = i & 511;
    int l = n >> 3, f = n & 7;
    g_Wt[n * WT_K + k] = __float2half(Wh[(size_t)l * (DIN * 8) + k * 8 + f]);
}

// ---------------- tensor-core GEMM (R12 proven: 50.3 us) ------------------------
#define GROWS 128
#define AKC   64
#define APAD  72
__global__ __launch_bounds__(256) void k_gemm(const float* __restrict__ x,
                                              const float* __restrict__ adst) {
    extern __shared__ char smem[];
    __half* As = (__half*)smem;                       // [128][72]
    __half* Ws = (__half*)(smem + GROWS * APAD * 2);  // [64][520]

    const int t = threadIdx.x;
    const int w = t >> 5;
    const int l = t & 31;
    const int row0 = blockIdx.x * GROWS;
    const int g = l >> 2;
    const int q = l & 3;

    {
        const uint4* src = (const uint4*)g_Wt;
#pragma unroll
        for (int i = 0; i < 16; i++) {
            int idx = i * 256 + t;
            int r = idx >> 6, c = idx & 63;
            *(uint4*)&Ws[r * WT_K + c * 8] = src[(r * WT_K + c * 8) >> 3];
        }
    }

    float acc[8][4];
#pragma unroll
    for (int n = 0; n < 8; n++)
#pragma unroll
        for (int j = 0; j < 4; j++) acc[n][j] = 0.f;

    const int arow = (l & 7) + ((l & 8) ? 8 : 0);
    const int acol = (l & 16) ? 8 : 0;

    const int pr_c4 = t & 15;
    const int pr_r0 = t >> 4;
    float4 pref[8];

#pragma unroll
    for (int i = 0; i < 8; i++) {
        int r = i * 16 + pr_r0;
        int rg = row0 + r; if (rg >= N_NODES) rg = N_NODES - 1;
        pref[i] = __ldcs((const float4*)&x[(size_t)rg * DIN + pr_c4 * 4]);
    }

    __syncthreads();   // Ws ready

    for (int kt = 0; kt < DIN; kt += AKC) {
#pragma unroll
        for (int i = 0; i < 8; i++) {
            int r = i * 16 + pr_r0;
            __half2* dst = (__half2*)&As[r * APAD + pr_c4 * 4];
            dst[0] = __floats2half2_rn(pref[i].x, pref[i].y);
            dst[1] = __floats2half2_rn(pref[i].z, pref[i].w);
        }
        __syncthreads();

        if (kt + AKC < DIN) {
#pragma unroll
            for (int i = 0; i < 8; i++) {
                int r = i * 16 + pr_r0;
                int rg = row0 + r; if (rg >= N_NODES) rg = N_NODES - 1;
                pref[i] = __ldcs((const float4*)&x[(size_t)rg * DIN + kt + AKC + pr_c4 * 4]);
            }
        }

#pragma unroll
        for (int k0 = 0; k0 < AKC; k0 += 16) {
            unsigned a0, a1, a2, a3;
            unsigned aaddr = __cvta_generic_to_shared(
                &As[(w * 16 + arow) * APAD + k0 + acol]);
            asm volatile("ldmatrix.sync.aligned.m8n8.x4.shared.b16 {%0,%1,%2,%3}, [%4];"
                         : "=r"(a0), "=r"(a1), "=r"(a2), "=r"(a3) : "r"(aaddr));
            int kg = kt + k0;
#pragma unroll
            for (int nt = 0; nt < 8; nt++) {
                int n = nt * 8 + g;
                unsigned b0 = *(const unsigned*)&Ws[n * WT_K + kg + 2 * q];
                unsigned b1 = *(const unsigned*)&Ws[n * WT_K + kg + 8 + 2 * q];
                asm volatile(
                    "mma.sync.aligned.m16n8k16.row.col.f32.f16.f16.f32 "
                    "{%0,%1,%2,%3}, {%4,%5,%6,%7}, {%8,%9}, {%0,%1,%2,%3};"
                    : "+f"(acc[nt][0]), "+f"(acc[nt][1]), "+f"(acc[nt][2]), "+f"(acc[nt][3])
                    : "r"(a0), "r"(a1), "r"(a2), "r"(a3), "r"(b0), "r"(b1));
            }
        }
        __syncthreads();
    }

    int row_lo = row0 + w * 16 + g;
    int row_hi = row_lo + 8;
#pragma unroll
    for (int nt = 0; nt < 8; nt++) {
        int c0 = nt * 8 + 2 * q, c1 = c0 + 1;
        if (row_lo < N_NODES)
            *(__half2*)&g_Hh[(size_t)row_lo * 64 + c0] = __floats2half2_rn(acc[nt][0], acc[nt][1]);
        if (row_hi < N_NODES)
            *(__half2*)&g_Hh[(size_t)row_hi * 64 + c0] = __floats2half2_rn(acc[nt][2], acc[nt][3]);
        float ad0 = adst[c0], ad1 = adst[c1];
        float psl_d = acc[nt][0] * ad0 + acc[nt][1] * ad1;
        float psh_d = acc[nt][2] * ad0 + acc[nt][3] * ad1;
        psl_d += __shfl_xor_sync(0xffffffffu, psl_d, 1);
        psl_d += __shfl_xor_sync(0xffffffffu, psl_d, 2);
        psh_d += __shfl_xor_sync(0xffffffffu, psh_d, 1);
        psh_d += __shfl_xor_sync(0xffffffffu, psh_d, 2);
        if (q == 0) {
            if (row_lo < N_NODES) g_ald[row_lo * 8 + nt] = psl_d;
            if (row_hi < N_NODES) g_ald[row_hi * 8 + nt] = psh_d;
        }
    }
}

// ---------------- layer 1: 8 lanes/node, lane = layer, 2-edge unrolled ----------
__global__ __launch_bounds__(256) void k_edge1v(const float* __restrict__ asrc,
                                                const float* __restrict__ bias_h,
                                                const float* __restrict__ Wout,
                                                const float* __restrict__ aso,
                                                const float* __restrict__ ado) {
    int tid = blockIdx.x * blockDim.x + threadIdx.x;
    int n = tid >> 3;
    int lj = tid & 7;

    float aldj = g_ald[n * 8 + lj];
    float as[8];
#pragma unroll
    for (int f = 0; f < 8; f++) as[f] = asrc[lj * 8 + f];

    float acc[8];
#pragma unroll
    for (int f = 0; f < 8; f++) acc[f] = 0.f;
    float sum = 0.f;

    int cnt = min(g_cnt[n], SLOT_CAP);
    const int* slots = &g_slots[(size_t)n * SLOT_CAP];
    int p = 0;
    for (; p + 2 <= cnt; p += 2) {
        int s0 = __ldg(&slots[p]);
        int s1 = __ldg(&slots[p + 1]);
        uint4 ha = *(const uint4*)&g_Hh[(size_t)s0 * 64 + lj * 8];
        uint4 hb = *(const uint4*)&g_Hh[(size_t)s1 * 64 + lj * 8];
        float2 a0 = h2f2(ha.x), a1 = h2f2(ha.y), a2 = h2f2(ha.z), a3 = h2f2(ha.w);
        float2 b0 = h2f2(hb.x), b1 = h2f2(hb.y), b2 = h2f2(hb.z), b3 = h2f2(hb.w);
        float alsa = a0.x * as[0] + a0.y * as[1] + a1.x * as[2] + a1.y * as[3]
                   + a2.x * as[4] + a2.y * as[5] + a3.x * as[6] + a3.y * as[7];
        float alsb = b0.x * as[0] + b0.y * as[1] + b1.x * as[2] + b1.y * as[3]
                   + b2.x * as[4] + b2.y * as[5] + b3.x * as[6] + b3.y * as[7];
        float eva = alsa + aldj; eva = (eva > 0.f) ? eva : NEG_SLOPE * eva;
        float evb = alsb + aldj; evb = (evb > 0.f) ? evb : NEG_SLOPE * evb;
        float wa = __expf(eva), wb = __expf(evb);
        sum += wa + wb;
        acc[0] = fmaf(wa, a0.x, fmaf(wb, b0.x, acc[0]));
        acc[1] = fmaf(wa, a0.y, fmaf(wb, b0.y, acc[1]));
        acc[2] = fmaf(wa, a1.x, fmaf(wb, b1.x, acc[2]));
        acc[3] = fmaf(wa, a1.y, fmaf(wb, b1.y, acc[3]));
        acc[4] = fmaf(wa, a2.x, fmaf(wb, b2.x, acc[4]));
        acc[5] = fmaf(wa, a2.y, fmaf(wb, b2.y, acc[5]));
        acc[6] = fmaf(wa, a3.x, fmaf(wb, b3.x, acc[6]));
        acc[7] = fmaf(wa, a3.y, fmaf(wb, b3.y, acc[7]));
    }
    if (p < cnt) {
        int s = __ldg(&slots[p]);
        uint4 h = *(const uint4*)&g_Hh[(size_t)s * 64 + lj * 8];
        float2 f0 = h2f2(h.x), f1 = h2f2(h.y), f2 = h2f2(h.z), f3 = h2f2(h.w);
        float als = f0.x * as[0] + f0.y * as[1] + f1.x * as[2] + f1.y * as[3]
                  + f2.x * as[4] + f2.y * as[5] + f3.x * as[6] + f3.y * as[7];
        float ev = als + aldj;
        ev = (ev > 0.f) ? ev : NEG_SLOPE * ev;
        float wv = __expf(ev);
        sum += wv;
        acc[0] = fmaf(wv, f0.x, acc[0]);
        acc[1] = fmaf(wv, f0.y, acc[1]);
        acc[2] = fmaf(wv, f1.x, acc[2]);
        acc[3] = fmaf(wv, f1.y, acc[3]);
        acc[4] = fmaf(wv, f2.x, acc[4]);
        acc[5] = fmaf(wv, f2.y, acc[5]);
        acc[6] = fmaf(wv, f3.x, acc[6]);
        acc[7] = fmaf(wv, f3.y, acc[7]);
    }

    float r = 1.f / sum;
    float tot[8];
#pragma unroll
    for (int f = 0; f < 8; f++) tot[f] = acc[f] * r + bias_h[lj * 8 + f];
#pragma unroll
    for (int o = 1; o < 8; o <<= 1)
#pragma unroll
        for (int f = 0; f < 8; f++)
            tot[f] += __shfl_xor_sync(0xffffffffu, tot[f], o);

    float h2[8];
#pragma unroll
    for (int f = 0; f < 8; f++) {
        float v = tot[f] * 0.125f;
        h2[f] = (v > 0.f) ? v : (__expf(v) - 1.f);
    }
    float c0 = 0.f, c1 = 0.f;
#pragma unroll
    for (int f = 0; f < 8; f++) {
        c0 = fmaf(h2[f], Wout[f * 16 + lj], c0);
        c1 = fmaf(h2[f], Wout[f * 16 + lj + 8], c1);
    }
    g_h3h[(size_t)n * 16 + lj]     = __float2half(c0);
    g_h3h[(size_t)n * 16 + lj + 8] = __float2half(c1);

    float ss = c0 * aso[lj] + c1 * aso[lj + 8];
    float dd = c0 * ado[lj] + c1 * ado[lj + 8];
#pragma unroll
    for (int o = 1; o < 8; o <<= 1) {
        ss += __shfl_xor_sync(0xffffffffu, ss, o);
        dd += __shfl_xor_sync(0xffffffffu, dd, o);
    }
    if (lj == 0) {
        g_al2s[n] = ss;
        g_al2d[n] = dd;
    }
}

// ---------------- layer 2: 4 lanes/node, lane = feature-quad, 2-edge unrolled ---
__global__ __launch_bounds__(128) void k_edge2v(const float* __restrict__ bias_o,
                                                float* __restrict__ out) {
    int tid = blockIdx.x * blockDim.x + threadIdx.x;
    int n = tid >> 2;
    int q4 = tid & 3;

    float al2d = g_al2d[n];

    float acc[4] = {0.f, 0.f, 0.f, 0.f};
    float sum = 0.f;

    int cnt = min(g_cnt[n], SLOT_CAP);
    const int* slots = &g_slots[(size_t)n * SLOT_CAP];
    int p = 0;
    for (; p + 2 <= cnt; p += 2) {
        int s0 = __ldg(&slots[p]);
        int s1 = __ldg(&slots[p + 1]);
        float la = g_al2s[s0];
        float lb = g_al2s[s1];
        uint2 ha = *(const uint2*)&g_h3h[(size_t)s0 * 16 + q4 * 4];
        uint2 hb = *(const uint2*)&g_h3h[(size_t)s1 * 16 + q4 * 4];
        float ta = la + al2d; ta = (ta > 0.f) ? ta : NEG_SLOPE * ta;
        float tb = lb + al2d; tb = (tb > 0.f) ? tb : NEG_SLOPE * tb;
        float wa = __expf(ta), wb = __expf(tb);
        sum += wa + wb;
        float2 a0 = h2f2(ha.x), a1 = h2f2(ha.y);
        float2 b0 = h2f2(hb.x), b1 = h2f2(hb.y);
        acc[0] = fmaf(wa, a0.x, fmaf(wb, b0.x, acc[0]));
        acc[1] = fmaf(wa, a0.y, fmaf(wb, b0.y, acc[1]));
        acc[2] = fmaf(wa, a1.x, fmaf(wb, b1.x, acc[2]));
        acc[3] = fmaf(wa, a1.y, fmaf(wb, b1.y, acc[3]));
    }
    if (p < cnt) {
        int s = __ldg(&slots[p]);
        float l2 = g_al2s[s];
        uint2 h = *(const uint2*)&g_h3h[(size_t)s * 16 + q4 * 4];
        float tv = l2 + al2d;
        tv = (tv > 0.f) ? tv : NEG_SLOPE * tv;
        float wv = __expf(tv);
        sum += wv;
        float2 f0 = h2f2(h.x), f1 = h2f2(h.y);
        acc[0] = fmaf(wv, f0.x, acc[0]);
        acc[1] = fmaf(wv, f0.y, acc[1]);
        acc[2] = fmaf(wv, f1.x, acc[2]);
        acc[3] = fmaf(wv, f1.y, acc[3]);
    }

    float rs = 1.f / sum;
    float o4[4];
#pragma unroll
    for (int c = 0; c < 4; c++) o4[c] = acc[c] * rs + bias_o[q4 * 4 + c];

    float m = fmaxf(fmaxf(o4[0], o4[1]), fmaxf(o4[2], o4[3]));
    m = fmaxf(m, __shfl_xor_sync(0xffffffffu, m, 1));
    m = fmaxf(m, __shfl_xor_sync(0xffffffffu, m, 2));
    float se = __expf(o4[0] - m) + __expf(o4[1] - m) + __expf(o4[2] - m) + __expf(o4[3] - m);
    se += __shfl_xor_sync(0xffffffffu, se, 1);
    se += __shfl_xor_sync(0xffffffffu, se, 2);
    float lse = __logf(se);
    *(float4*)&out[(size_t)n * 16 + q4 * 4] =
        make_float4(o4[0] - m - lse, o4[1] - m - lse, o4[2] - m - lse, o4[3] - m - lse);
}

// ---------------- launch ---------------------------------------------------------
#define GEMM_SMEM (GROWS * APAD * 2 + 64 * WT_K * 2)

extern "C" void kernel_launch(void* const* d_in, const int* in_sizes, int n_in,
                              void* d_out, int out_size) {
    const float* x    = (const float*)d_in[0];
    const void*  ei   = d_in[1];
    const float* Wh   = (const float*)d_in[2];
    const float* asrc = (const float*)d_in[3];
    const float* adst = (const float*)d_in[4];
    const float* bh   = (const float*)d_in[5];
    const float* Wout = (const float*)d_in[6];
    const float* aso  = (const float*)d_in[7];
    const float* ado  = (const float*)d_in[8];
    const float* bo   = (const float*)d_in[9];
    float*       out  = (float*)d_out;

    static int smem_set = 0;
    if (!smem_set) {
        cudaFuncSetAttribute(k_gemm, cudaFuncAttributeMaxDynamicSharedMemorySize, GEMM_SMEM);
        smem_set = 1;
    }

    cudaStream_t s2;
    cudaStreamCreateWithFlags(&s2, cudaStreamNonBlocking);
    cudaEvent_t evA, evB;
    cudaEventCreateWithFlags(&evA, cudaEventDisableTiming);
    cudaEventCreateWithFlags(&evB, cudaEventDisableTiming);

    cudaEventRecord(evA, 0);
    cudaStreamWaitEvent(s2, evA, 0);

    // side stream: counter clear + single-pass bucket scatter (no count/scan)
    void* p_cnt;
    cudaGetSymbolAddress(&p_cnt, g_cnt);
    cudaMemsetAsync(p_cnt, 0, sizeof(int) * N_NODES, s2);             // 1
    k_scatter<<<(ET + 255) / 256, 256, 0, s2>>>(ei);                   // 2 (s2)
    cudaEventRecord(evB, s2);

    // main stream: weights + GEMM
    k_prep_w<<<(64 * DIN + 255) / 256, 256>>>(Wh);                     // 3
    k_gemm<<<(N_NODES + GROWS - 1) / GROWS, 256, GEMM_SMEM>>>(x, adst);// 4

    cudaStreamWaitEvent(0, evB, 0);
    k_edge1v<<<(N_NODES * 8) / 256, 256>>>(asrc, bh, Wout, aso, ado);  // 5
    k_edge2v<<<(N_NODES * 4) / 128, 128>>>(bo, out);                   // 6
}

// round 16
// speedup vs baseline: 1.2049x; 1.0298x over previous
#include <cuda_runtime.h>
#include <cuda_fp16.h>
#include <math.h>

#define N_NODES 100000
#define DIN     512
#define NE      1600000
#define ET      (NE + N_NODES)   // edges + self loops
#define NEG_SLOPE 0.2f
#define WT_K    520              // padded k stride
#define SLOT_CAP 128             // per-node bucket capacity (P(deg>=128) ~ 1e-63)

// ---------------- scratch (device globals) -------------------------------------
__device__ __align__(128) __half g_Wt[64 * WT_K];              // W^T as half [n][k]
__device__ __align__(128) __half g_Hh[(size_t)N_NODES * 64];   // fp16 messages L1
__device__ __align__(128) float  g_als[N_NODES * 8];           // src logits (layer-major)
__device__ __align__(128) float  g_ald[N_NODES * 8];
__device__ __align__(128) __half g_h3h[(size_t)N_NODES * 16];  // fp16 messages L2
__device__ __align__(128) float  g_al2s[N_NODES];
__device__ __align__(128) float  g_al2d[N_NODES];
__device__ int g_slots[(size_t)N_NODES * SLOT_CAP];            // bucket CSR
__device__ int g_cnt[N_NODES];

__device__ __forceinline__ float2 h2f2(unsigned u) {
    __half2 h = *reinterpret_cast<const __half2*>(&u);
    return __half22float2(h);
}

// Per-block edge-index dtype detection (JAX x64-off downcast)
__device__ __forceinline__ int detect_is64(const int* ei32) {
    int allzero = 1;
#pragma unroll 8
    for (int i = 0; i < 64; i++)
        if (__ldg(&ei32[2 * i + 1]) != 0) { allzero = 0; break; }
    return allzero;
}

__device__ __forceinline__ void decode_edge(const void* ei, int is64, int e,
                                            int* s, int* d) {
    if (e < NE) {
        int sv, dv;
        if (is64) {
            const long long* p = (const long long*)ei;
            sv = (int)p[e];
            dv = (int)p[(size_t)NE + e];
        } else {
            const int* p = (const int*)ei;
            sv = p[e];
            dv = p[NE + e];
        }
        *s = min(max(sv, 0), N_NODES - 1);
        *d = min(max(dv, 0), N_NODES - 1);
    } else {
        *s = e - NE;
        *d = e - NE;
    }
}

// ---------------- single-pass bucket scatter (no count, no scan) ----------------
__global__ void k_scatter(const void* __restrict__ ei) {
    int is64 = detect_is64((const int*)ei);
    int e = blockIdx.x * blockDim.x + threadIdx.x;
    if (e >= ET) return;
    int s, d;
    decode_edge(ei, is64, e, &s, &d);
    int pos = atomicAdd(&g_cnt[d], 1);
    if (pos < SLOT_CAP)
        g_slots[(size_t)d * SLOT_CAP + pos] = s;
}

// g_Wt[n][k] = (half) W_hidden[n/8][k][n%8]   (unpacked: conflict-free LDS.32)
__global__ void k_prep_w(const float* __restrict__ Wh) {
    int i = blockIdx.x * blockDim.x + threadIdx.x;
    if (i >= 64 * DIN) return;
    int n = i >> 9, k = i & 511;
    int l = n >> 3, f = n & 7;
    g_Wt[n * WT_K + k] = __float2half(Wh[(size_t)l * (DIN * 8) + k * 8 + f]);
}

// ---------------- tensor-core GEMM (proven mainloop; epilogue emits als+ald) ----
#define GROWS 128
#define AKC   64
#define APAD  72
__global__ __launch_bounds__(256) void k_gemm(const float* __restrict__ x,
                                              const float* __restrict__ asrc,
                                              const float* __restrict__ adst) {
    extern __shared__ char smem[];
    __half* As = (__half*)smem;                       // [128][72]
    __half* Ws = (__half*)(smem + GROWS * APAD * 2);  // [64][520]

    const int t = threadIdx.x;
    const int w = t >> 5;
    const int l = t & 31;
    const int row0 = blockIdx.x * GROWS;
    const int g = l >> 2;
    const int q = l & 3;

    {
        const uint4* src = (const uint4*)g_Wt;
#pragma unroll
        for (int i = 0; i < 16; i++) {
            int idx = i * 256 + t;
            int r = idx >> 6, c = idx & 63;
            *(uint4*)&Ws[r * WT_K + c * 8] = src[(r * WT_K + c * 8) >> 3];
        }
    }

    float acc[8][4];
#pragma unroll
    for (int n = 0; n < 8; n++)
#pragma unroll
        for (int j = 0; j < 4; j++) acc[n][j] = 0.f;

    const int arow = (l & 7) + ((l & 8) ? 8 : 0);
    const int acol = (l & 16) ? 8 : 0;

    const int pr_c4 = t & 15;
    const int pr_r0 = t >> 4;
    float4 pref[8];

#pragma unroll
    for (int i = 0; i < 8; i++) {
        int r = i * 16 + pr_r0;
        int rg = row0 + r; if (rg >= N_NODES) rg = N_NODES - 1;
        pref[i] = __ldcs((const float4*)&x[(size_t)rg * DIN + pr_c4 * 4]);
    }

    __syncthreads();   // Ws ready

    for (int kt = 0; kt < DIN; kt += AKC) {
#pragma unroll
        for (int i = 0; i < 8; i++) {
            int r = i * 16 + pr_r0;
            __half2* dst = (__half2*)&As[r * APAD + pr_c4 * 4];
            dst[0] = __floats2half2_rn(pref[i].x, pref[i].y);
            dst[1] = __floats2half2_rn(pref[i].z, pref[i].w);
        }
        __syncthreads();

        if (kt + AKC < DIN) {
#pragma unroll
            for (int i = 0; i < 8; i++) {
                int r = i * 16 + pr_r0;
                int rg = row0 + r; if (rg >= N_NODES) rg = N_NODES - 1;
                pref[i] = __ldcs((const float4*)&x[(size_t)rg * DIN + kt + AKC + pr_c4 * 4]);
            }
        }

#pragma unroll
        for (int k0 = 0; k0 < AKC; k0 += 16) {
            unsigned a0, a1, a2, a3;
            unsigned aaddr = __cvta_generic_to_shared(
                &As[(w * 16 + arow) * APAD + k0 + acol]);
            asm volatile("ldmatrix.sync.aligned.m8n8.x4.shared.b16 {%0,%1,%2,%3}, [%4];"
                         : "=r"(a0), "=r"(a1), "=r"(a2), "=r"(a3) : "r"(aaddr));
            int kg = kt + k0;
#pragma unroll
            for (int nt = 0; nt < 8; nt++) {
                int n = nt * 8 + g;
                unsigned b0 = *(const unsigned*)&Ws[n * WT_K + kg + 2 * q];
                unsigned b1 = *(const unsigned*)&Ws[n * WT_K + kg + 8 + 2 * q];
                asm volatile(
                    "mma.sync.aligned.m16n8k16.row.col.f32.f16.f16.f32 "
                    "{%0,%1,%2,%3}, {%4,%5,%6,%7}, {%8,%9}, {%0,%1,%2,%3};"
                    : "+f"(acc[nt][0]), "+f"(acc[nt][1]), "+f"(acc[nt][2]), "+f"(acc[nt][3])
                    : "r"(a0), "r"(a1), "r"(a2), "r"(a3), "r"(b0), "r"(b1));
            }
        }
        __syncthreads();
    }

    int row_lo = row0 + w * 16 + g;
    int row_hi = row_lo + 8;
#pragma unroll
    for (int nt = 0; nt < 8; nt++) {
        int c0 = nt * 8 + 2 * q, c1 = c0 + 1;
        if (row_lo < N_NODES)
            *(__half2*)&g_Hh[(size_t)row_lo * 64 + c0] = __floats2half2_rn(acc[nt][0], acc[nt][1]);
        if (row_hi < N_NODES)
            *(__half2*)&g_Hh[(size_t)row_hi * 64 + c0] = __floats2half2_rn(acc[nt][2], acc[nt][3]);
        float as0 = asrc[c0], as1 = asrc[c1];
        float ad0 = adst[c0], ad1 = adst[c1];
        float psl_s = acc[nt][0] * as0 + acc[nt][1] * as1;
        float psl_d = acc[nt][0] * ad0 + acc[nt][1] * ad1;
        float psh_s = acc[nt][2] * as0 + acc[nt][3] * as1;
        float psh_d = acc[nt][2] * ad0 + acc[nt][3] * ad1;
        psl_s += __shfl_xor_sync(0xffffffffu, psl_s, 1);
        psl_s += __shfl_xor_sync(0xffffffffu, psl_s, 2);
        psl_d += __shfl_xor_sync(0xffffffffu, psl_d, 1);
        psl_d += __shfl_xor_sync(0xffffffffu, psl_d, 2);
        psh_s += __shfl_xor_sync(0xffffffffu, psh_s, 1);
        psh_s += __shfl_xor_sync(0xffffffffu, psh_s, 2);
        psh_d += __shfl_xor_sync(0xffffffffu, psh_d, 1);
        psh_d += __shfl_xor_sync(0xffffffffu, psh_d, 2);
        if (q == 0) {
            if (row_lo < N_NODES) { g_als[row_lo * 8 + nt] = psl_s; g_ald[row_lo * 8 + nt] = psl_d; }
            if (row_hi < N_NODES) { g_als[row_hi * 8 + nt] = psh_s; g_ald[row_hi * 8 + nt] = psh_d; }
        }
    }
}

// ---------------- layer 1: 8 lanes/node, lane = layer, 2-edge unrolled ----------
// als precomputed (GEMM epilogue): per edge just 1 broadcast-line float LDG,
// removing 8 FMAs/lane/edge from the issue-bound loop.
__global__ __launch_bounds__(256) void k_edge1v(const float* __restrict__ bias_h,
                                                const float* __restrict__ Wout,
                                                const float* __restrict__ aso,
                                                const float* __restrict__ ado) {
    int tid = blockIdx.x * blockDim.x + threadIdx.x;
    int n = tid >> 3;
    int lj = tid & 7;

    float aldj = g_ald[n * 8 + lj];

    float acc[8];
#pragma unroll
    for (int f = 0; f < 8; f++) acc[f] = 0.f;
    float sum = 0.f;

    int cnt = min(g_cnt[n], SLOT_CAP);
    const int* slots = &g_slots[(size_t)n * SLOT_CAP];
    int p = 0;
    for (; p + 2 <= cnt; p += 2) {
        int s0 = __ldg(&slots[p]);
        int s1 = __ldg(&slots[p + 1]);
        float alsa = g_als[s0 * 8 + lj];
        float alsb = g_als[s1 * 8 + lj];
        uint4 ha = *(const uint4*)&g_Hh[(size_t)s0 * 64 + lj * 8];
        uint4 hb = *(const uint4*)&g_Hh[(size_t)s1 * 64 + lj * 8];
        float eva = alsa + aldj; eva = (eva > 0.f) ? eva : NEG_SLOPE * eva;
        float evb = alsb + aldj; evb = (evb > 0.f) ? evb : NEG_SLOPE * evb;
        float wa = __expf(eva), wb = __expf(evb);
        sum += wa + wb;
        float2 a0 = h2f2(ha.x), a1 = h2f2(ha.y), a2 = h2f2(ha.z), a3 = h2f2(ha.w);
        float2 b0 = h2f2(hb.x), b1 = h2f2(hb.y), b2 = h2f2(hb.z), b3 = h2f2(hb.w);
        acc[0] = fmaf(wa, a0.x, fmaf(wb, b0.x, acc[0]));
        acc[1] = fmaf(wa, a0.y, fmaf(wb, b0.y, acc[1]));
        acc[2] = fmaf(wa, a1.x, fmaf(wb, b1.x, acc[2]));
        acc[3] = fmaf(wa, a1.y, fmaf(wb, b1.y, acc[3]));
        acc[4] = fmaf(wa, a2.x, fmaf(wb, b2.x, acc[4]));
        acc[5] = fmaf(wa, a2.y, fmaf(wb, b2.y, acc[5]));
        acc[6] = fmaf(wa, a3.x, fmaf(wb, b3.x, acc[6]));
        acc[7] = fmaf(wa, a3.y, fmaf(wb, b3.y, acc[7]));
    }
    if (p < cnt) {
        int s = __ldg(&slots[p]);
        float als = g_als[s * 8 + lj];
        uint4 h = *(const uint4*)&g_Hh[(size_t)s * 64 + lj * 8];
        float ev = als + aldj;
        ev = (ev > 0.f) ? ev : NEG_SLOPE * ev;
        float wv = __expf(ev);
        sum += wv;
        float2 f0 = h2f2(h.x), f1 = h2f2(h.y), f2 = h2f2(h.z), f3 = h2f2(h.w);
        acc[0] = fmaf(wv, f0.x, acc[0]);
        acc[1] = fmaf(wv, f0.y, acc[1]);
        acc[2] = fmaf(wv, f1.x, acc[2]);
        acc[3] = fmaf(wv, f1.y, acc[3]);
        acc[4] = fmaf(wv, f2.x, acc[4]);
        acc[5] = fmaf(wv, f2.y, acc[5]);
        acc[6] = fmaf(wv, f3.x, acc[6]);
        acc[7] = fmaf(wv, f3.y, acc[7]);
    }

    float r = 1.f / sum;
    float tot[8];
#pragma unroll
    for (int f = 0; f < 8; f++) tot[f] = acc[f] * r + bias_h[lj * 8 + f];
#pragma unroll
    for (int o = 1; o < 8; o <<= 1)
#pragma unroll
        for (int f = 0; f < 8; f++)
            tot[f] += __shfl_xor_sync(0xffffffffu, tot[f], o);

    float h2[8];
#pragma unroll
    for (int f = 0; f < 8; f++) {
        float v = tot[f] * 0.125f;
        h2[f] = (v > 0.f) ? v : (__expf(v) - 1.f);
    }
    float c0 = 0.f, c1 = 0.f;
#pragma unroll
    for (int f = 0; f < 8; f++) {
        c0 = fmaf(h2[f], Wout[f * 16 + lj], c0);
        c1 = fmaf(h2[f], Wout[f * 16 + lj + 8], c1);
    }
    g_h3h[(size_t)n * 16 + lj]     = __float2half(c0);
    g_h3h[(size_t)n * 16 + lj + 8] = __float2half(c1);

    float ss = c0 * aso[lj] + c1 * aso[lj + 8];
    float dd = c0 * ado[lj] + c1 * ado[lj + 8];
#pragma unroll
    for (int o = 1; o < 8; o <<= 1) {
        ss += __shfl_xor_sync(0xffffffffu, ss, o);
        dd += __shfl_xor_sync(0xffffffffu, dd, o);
    }
    if (lj == 0) {
        g_al2s[n] = ss;
        g_al2d[n] = dd;
    }
}

// ---------------- layer 2: 4 lanes/node, lane = feature-quad, 2-edge unrolled ---
__global__ __launch_bounds__(128) void k_edge2v(const float* __restrict__ bias_o,
                                                float* __restrict__ out) {
    int tid = blockIdx.x * blockDim.x + threadIdx.x;
    int n = tid >> 2;
    int q4 = tid & 3;

    float al2d = g_al2d[n];

    float acc[4] = {0.f, 0.f, 0.f, 0.f};
    float sum = 0.f;

    int cnt = min(g_cnt[n], SLOT_CAP);
    const int* slots = &g_slots[(size_t)n * SLOT_CAP];
    int p = 0;
    for (; p + 2 <= cnt; p += 2) {
        int s0 = __ldg(&slots[p]);
        int s1 = __ldg(&slots[p + 1]);
        float la = g_al2s[s0];
        float lb = g_al2s[s1];
        uint2 ha = *(const uint2*)&g_h3h[(size_t)s0 * 16 + q4 * 4];
        uint2 hb = *(const uint2*)&g_h3h[(size_t)s1 * 16 + q4 * 4];
        float ta = la + al2d; ta = (ta > 0.f) ? ta : NEG_SLOPE * ta;
        float tb = lb + al2d; tb = (tb > 0.f) ? tb : NEG_SLOPE * tb;
        float wa = __expf(ta), wb = __expf(tb);
        sum += wa + wb;
        float2 a0 = h2f2(ha.x), a1 = h2f2(ha.y);
        float2 b0 = h2f2(hb.x), b1 = h2f2(hb.y);
        acc[0] = fmaf(wa, a0.x, fmaf(wb, b0.x, acc[0]));
        acc[1] = fmaf(wa, a0.y, fmaf(wb, b0.y, acc[1]));
        acc[2] = fmaf(wa, a1.x, fmaf(wb, b1.x, acc[2]));
        acc[3] = fmaf(wa, a1.y, fmaf(wb, b1.y, acc[3]));
    }
    if (p < cnt) {
        int s = __ldg(&slots[p]);
        float l2 = g_al2s[s];
        uint2 h = *(const uint2*)&g_h3h[(size_t)s * 16 + q4 * 4];
        float tv = l2 + al2d;
        tv = (tv > 0.f) ? tv : NEG_SLOPE * tv;
        float wv = __expf(tv);
        sum += wv;
        float2 f0 = h2f2(h.x), f1 = h2f2(h.y);
        acc[0] = fmaf(wv, f0.x, acc[0]);
        acc[1] = fmaf(wv, f0.y, acc[1]);
        acc[2] = fmaf(wv, f1.x, acc[2]);
        acc[3] = fmaf(wv, f1.y, acc[3]);
    }

    float rs = 1.f / sum;
    float o4[4];
#pragma unroll
    for (int c = 0; c < 4; c++) o4[c] = acc[c] * rs + bias_o[q4 * 4 + c];

    float m = fmaxf(fmaxf(o4[0], o4[1]), fmaxf(o4[2], o4[3]));
    m = fmaxf(m, __shfl_xor_sync(0xffffffffu, m, 1));
    m = fmaxf(m, __shfl_xor_sync(0xffffffffu, m, 2));
    float se = __expf(o4[0] - m) + __expf(o4[1] - m) + __expf(o4[2] - m) + __expf(o4[3] - m);
    se += __shfl_xor_sync(0xffffffffu, se, 1);
    se += __shfl_xor_sync(0xffffffffu, se, 2);
    float lse = __logf(se);
    *(float4*)&out[(size_t)n * 16 + q4 * 4] =
        make_float4(o4[0] - m - lse, o4[1] - m - lse, o4[2] - m - lse, o4[3] - m - lse);
}

// ---------------- launch ---------------------------------------------------------
#define GEMM_SMEM (GROWS * APAD * 2 + 64 * WT_K * 2)

extern "C" void kernel_launch(void* const* d_in, const int* in_sizes, int n_in,
                              void* d_out, int out_size) {
    const float* x    = (const float*)d_in[0];
    const void*  ei   = d_in[1];
    const float* Wh   = (const float*)d_in[2];
    const float* asrc = (const float*)d_in[3];
    const float* adst = (const float*)d_in[4];
    const float* bh   = (const float*)d_in[5];
    const float* Wout = (const float*)d_in[6];
    const float* aso  = (const float*)d_in[7];
    const float* ado  = (const float*)d_in[8];
    const float* bo   = (const float*)d_in[9];
    float*       out  = (float*)d_out;

    static int smem_set = 0;
    if (!smem_set) {
        cudaFuncSetAttribute(k_gemm, cudaFuncAttributeMaxDynamicSharedMemorySize, GEMM_SMEM);
        smem_set = 1;
    }

    cudaStream_t s2;
    cudaStreamCreateWithFlags(&s2, cudaStreamNonBlocking);
    cudaEvent_t evA, evB;
    cudaEventCreateWithFlags(&evA, cudaEventDisableTiming);
    cudaEventCreateWithFlags(&evB, cudaEventDisableTiming);

    cudaEventRecord(evA, 0);
    cudaStreamWaitEvent(s2, evA, 0);

    // side stream: counter clear + single-pass bucket scatter
    void* p_cnt;
    cudaGetSymbolAddress(&p_cnt, g_cnt);
    cudaMemsetAsync(p_cnt, 0, sizeof(int) * N_NODES, s2);             // 1
    k_scatter<<<(ET + 255) / 256, 256, 0, s2>>>(ei);                   // 2 (s2)
    cudaEventRecord(evB, s2);

    // main stream: weights + GEMM (emits H, als, ald)
    k_prep_w<<<(64 * DIN + 255) / 256, 256>>>(Wh);                     // 3
    k_gemm<<<(N_NODES + GROWS - 1) / GROWS, 256, GEMM_SMEM>>>(x, asrc, adst); // 4

    cudaStreamWaitEvent(0, evB, 0);
    k_edge1v<<<(N_NODES * 8) / 256, 256>>>(bh, Wout, aso, ado);        // 5
    k_edge2v<<<(N_NODES * 4) / 128, 128>>>(bo, out);                   // 6
}